// round 13
// baseline (speedup 1.0000x reference)
#include <cuda_runtime.h>
#include <cstdint>

// DigitCaps dynamic routing, fused, 2-pass routing iterations.
// c_t = softmax_j(u_hat . Vsum_t);  s_t = sum_i c_t * u_hat
// Pass A: compute+store c (4 batches/thread). Pass B: FIRST-style weighted
// accumulation using identity sum_i c*(sum_e u_e W) = sum_e (c*u_e) W.

#define B_      512
#define NI      1152
#define NJ      10
#define DI      8
#define DO      16

#define THREADS 256
#define BTF     16       // batches per block (FIRST / passA / passB)
#define G_      6
#define ISPLITS 8
#define ICHUNK  144
#define NCHUNK  24
#define NCHUNK_TOTAL (ISPLITS * NCHUNK)
#define NPART   ISPLITS

#define WTILE_ULL  644
#define WBUF_ULL   (G_ * WTILE_ULL)
#define WBUF       (WBUF_ULL * 2)
#define NBUF    3
#define VROW    18
#define CHUNK_BYTES (WBUF * 4)
#define MBAR_OFF   (NBUF * WBUF + BTF * NJ * VROW)
#define SMEM_WORDS (MBAR_OFF + 8)

__device__ float g_wpad[(size_t)NCHUNK_TOTAL * WBUF];
__device__ float g_partial[(size_t)B_ * NPART * NJ * DO];
__device__ float g_vsum[B_ * NJ * DO];
__device__ float g_c[(size_t)B_ * NI * NJ];   // routing coefficients (23.6 MB)

using ull = unsigned long long;

__device__ __forceinline__ ull fma2(ull a, ull b, ull c) {
    ull d; asm("fma.rn.f32x2 %0, %1, %2, %3;" : "=l"(d) : "l"(a), "l"(b), "l"(c)); return d;
}
__device__ __forceinline__ ull add2(ull a, ull b) {
    ull d; asm("add.rn.f32x2 %0, %1, %2;" : "=l"(d) : "l"(a), "l"(b)); return d;
}
__device__ __forceinline__ ull bcast2(float x) {
    ull d; asm("mov.b64 %0, {%1, %1};" : "=l"(d) : "f"(x)); return d;
}
__device__ __forceinline__ ull pack2(float x, float y) {
    ull d; asm("mov.b64 %0, {%1, %2};" : "=l"(d) : "f"(x), "f"(y)); return d;
}
__device__ __forceinline__ float sum2(ull a) {
    float l, h; asm("mov.b64 {%0, %1}, %2;" : "=f"(l), "=f"(h) : "l"(a)); return l + h;
}
__device__ __forceinline__ void st2(float* p, ull v) { *(ull*)p = v; }

__device__ __forceinline__ void mbar_init(uint32_t addr, uint32_t count) {
    asm volatile("mbarrier.init.shared.b64 [%0], %1;" :: "r"(addr), "r"(count) : "memory");
}
__device__ __forceinline__ void mbar_wait(uint32_t addr, uint32_t parity) {
    asm volatile(
        "{\n\t.reg .pred P;\n\t"
        "WL_%=:\n\t"
        "mbarrier.try_wait.parity.acquire.cta.shared::cta.b64 P, [%0], %1, 0x989680;\n\t"
        "@P bra.uni WD_%=;\n\t"
        "bra.uni WL_%=;\n\t"
        "WD_%=:\n\t}"
        :: "r"(addr), "r"(parity) : "memory");
}

__device__ __forceinline__ void issue_chunk(int chunk, int slot,
                                            uint32_t sbase, uint32_t mbase, int tid) {
    if (tid == 0) {
        uint32_t mbar = mbase + slot * 8;
        asm volatile("mbarrier.arrive.expect_tx.shared.b64 _, [%0], %1;"
                     :: "r"(mbar), "r"((uint32_t)CHUNK_BYTES) : "memory");
        const float* src = g_wpad + (size_t)chunk * WBUF;
        uint32_t dst = sbase + (uint32_t)(slot * WBUF) * 4;
        asm volatile(
            "cp.async.bulk.shared::cluster.global.mbarrier::complete_tx::bytes "
            "[%0], [%1], %2, [%3];"
            :: "r"(dst), "l"(src), "r"((uint32_t)CHUNK_BYTES), "r"(mbar) : "memory");
    }
}

// W[i][j][e][d] -> g_wpad ull[chunk*WBUF_ULL + g*644 + e*80 + k*10 + j]
__global__ void prepack_kernel(const float* __restrict__ W) {
    int t = blockIdx.x * blockDim.x + threadIdx.x;
    if (t >= NI * NJ * DI) return;
    int e = t % DI;
    int r = t / DI;
    int j = r % NJ;
    int i = r / NJ;
    int chunk = i / G_;
    int g = i - chunk * G_;
    const float4* src = (const float4*)(W + (((size_t)(i * NJ + j)) * DI + e) * DO);
    float4 v0 = src[0], v1 = src[1], v2 = src[2], v3 = src[3];
    ull* dst = (ull*)g_wpad + (size_t)chunk * WBUF_ULL + g * WTILE_ULL + e * 80 + j;
    dst[0]  = pack2(v0.x, v0.y);
    dst[10] = pack2(v0.z, v0.w);
    dst[20] = pack2(v1.x, v1.y);
    dst[30] = pack2(v1.z, v1.w);
    dst[40] = pack2(v2.x, v2.y);
    dst[50] = pack2(v2.z, v2.w);
    dst[60] = pack2(v3.x, v3.y);
    dst[70] = pack2(v3.z, v3.w);
}

// ---- weighted-sum sweep: sacc += sum_e (c*u_e) W.  FIRST: c = 0.1 uniform. ----
template <bool FIRST>
__global__ void __launch_bounds__(THREADS, 2)
sweepB_kernel(const float* __restrict__ u) {
    extern __shared__ float smem[];
    float* wst = smem;
    float* red = smem;

    const int tid  = threadIdx.x;
    const int lane = tid & 31;
    const int warp = tid >> 5;
    const int seg  = lane / 10;
    const bool active = (seg < 3);
    const int j    = lane - seg * 10;
    const int unit = warp * 3 + (active ? seg : 0);
    const int bq   = unit & 3;
    const int g    = unit >> 2;

    const int c0g   = blockIdx.x * NCHUNK;
    const int i0    = blockIdx.x * ICHUNK;
    const int bbase = blockIdx.y * BTF;

    uint32_t smem_base = (uint32_t)__cvta_generic_to_shared(wst);
    uint32_t mbar_base = (uint32_t)__cvta_generic_to_shared(smem + MBAR_OFF);

    if (tid == 0) {
        mbar_init(mbar_base + 0, 1);
        mbar_init(mbar_base + 8, 1);
        mbar_init(mbar_base + 16, 1);
    }
    __syncthreads();

    issue_chunk(c0g, 0, smem_base, mbar_base, tid);
    issue_chunk(c0g + 1, 1, smem_base, mbar_base, tid);

    ull sacc[4][8];
    #pragma unroll
    for (int b = 0; b < 4; b++)
        #pragma unroll
        for (int k = 0; k < 8; k++) sacc[b][k] = 0ULL;

    const int b0 = bbase + bq * 4;
    const float* up = u + (size_t)b0 * NI * DI;

    for (int c = 0; c < NCHUNK; c++) {
        const int buf = c % NBUF;
        const int i = i0 + c * G_ + g;

        float ur[4][8];
        if (active) {
            #pragma unroll
            for (int b = 0; b < 4; b++) {
                const float4* s = (const float4*)(up + (size_t)b * NI * DI + (size_t)i * DI);
                float4 x = s[0], y = s[1];
                float cw = 1.0f;
                if (!FIRST) cw = g_c[((size_t)(b0 + b) * NI + i) * NJ + j];
                ur[b][0]=x.x*cw; ur[b][1]=x.y*cw; ur[b][2]=x.z*cw; ur[b][3]=x.w*cw;
                ur[b][4]=y.x*cw; ur[b][5]=y.y*cw; ur[b][6]=y.z*cw; ur[b][7]=y.w*cw;
            }
        }

        __syncthreads();
        if (c + 2 < NCHUNK)
            issue_chunk(c0g + c + 2, (c + 2) % NBUF, smem_base, mbar_base, tid);

        mbar_wait(mbar_base + buf * 8, (c / NBUF) & 1);

        if (active) {
            const ull* wt = (const ull*)(wst + buf * WBUF) + g * WTILE_ULL + j;
            #pragma unroll
            for (int e = 0; e < 8; e++) {
                const ull* wte = wt + e * 80;
                ull ue0 = bcast2(ur[0][e]);
                ull ue1 = bcast2(ur[1][e]);
                ull ue2 = bcast2(ur[2][e]);
                ull ue3 = bcast2(ur[3][e]);
                #pragma unroll
                for (int k = 0; k < 8; k++) {
                    ull wv = wte[k * 10];
                    sacc[0][k] = fma2(ue0, wv, sacc[0][k]);
                    sacc[1][k] = fma2(ue1, wv, sacc[1][k]);
                    sacc[2][k] = fma2(ue2, wv, sacc[2][k]);
                    sacc[3][k] = fma2(ue3, wv, sacc[3][k]);
                }
            }
        }
    }

    __syncthreads();
    if (active) {
        #pragma unroll
        for (int b = 0; b < 4; b++) {
            int r = ((bq * 4 + b) * 6 + g) * 10 + j;
            #pragma unroll
            for (int k = 0; k < 8; k++)
                st2(red + r * 16 + 2 * k, sacc[b][k]);
        }
    }
    __syncthreads();

    #pragma unroll 1
    for (int idx = tid; idx < BTF * NJ * DO; idx += THREADS) {
        int d  = idx & 15;
        int r  = idx >> 4;
        int jj = r % 10;
        int bt = r / 10;
        float s = 0.f;
        #pragma unroll
        for (int gg = 0; gg < 6; gg++)
            s += red[((bt * 6 + gg) * 10 + jj) * 16 + d];
        if (FIRST) s *= 0.1f;
        int b = bbase + bt;
        g_partial[((size_t)(b * NPART + blockIdx.x) * NJ + jj) * DO + d] = s;
    }
}

// ---- pass A: compute u_hat, logit = u_hat.Vsum, softmax over j, store c ----
__global__ void __launch_bounds__(THREADS, 2)
sweepA_kernel(const float* __restrict__ u) {
    extern __shared__ float smem[];
    float* wst = smem;
    float* vsm = smem + NBUF * WBUF;

    const int tid  = threadIdx.x;
    const int lane = tid & 31;
    const int warp = tid >> 5;
    const int seg  = lane / 10;
    const bool active = (seg < 3);
    const int j    = lane - seg * 10;
    const int unit = warp * 3 + (active ? seg : 0);
    const int bq   = unit & 3;
    const int g    = unit >> 2;

    const int base = seg * 10;
    const int sl5 = base + (j >= 5 ? j - 5 : j + 5);
    const int sl1 = base + (j >= 9 ? j - 9 : j + 1);
    const int sl2 = base + (j >= 8 ? j - 8 : j + 2);
    const int sl4 = base + (j >= 6 ? j - 6 : j + 4);

    const int c0g   = blockIdx.x * NCHUNK;
    const int i0    = blockIdx.x * ICHUNK;
    const int bbase = blockIdx.y * BTF;

    uint32_t smem_base = (uint32_t)__cvta_generic_to_shared(wst);
    uint32_t mbar_base = (uint32_t)__cvta_generic_to_shared(smem + MBAR_OFF);

    if (tid == 0) {
        mbar_init(mbar_base + 0, 1);
        mbar_init(mbar_base + 8, 1);
        mbar_init(mbar_base + 16, 1);
    }
    for (int idx = tid; idx < BTF * NJ * DO; idx += THREADS) {
        vsm[(idx >> 4) * VROW + (idx & 15)] = g_vsum[bbase * NJ * DO + idx];
    }
    __syncthreads();

    issue_chunk(c0g, 0, smem_base, mbar_base, tid);
    issue_chunk(c0g + 1, 1, smem_base, mbar_base, tid);

    const int b0 = bbase + bq * 4;
    const float* up = u + (size_t)b0 * NI * DI;
    const float* vsb0 = vsm + ((bq * 4) * NJ + j) * VROW;

    for (int c = 0; c < NCHUNK; c++) {
        const int buf = c % NBUF;
        const int i = i0 + c * G_ + g;

        float ur[4][8];
        if (active) {
            #pragma unroll
            for (int b = 0; b < 4; b++) {
                const float4* s = (const float4*)(up + (size_t)b * NI * DI + (size_t)i * DI);
                float4 x = s[0], y = s[1];
                ur[b][0]=x.x; ur[b][1]=x.y; ur[b][2]=x.z; ur[b][3]=x.w;
                ur[b][4]=y.x; ur[b][5]=y.y; ur[b][6]=y.z; ur[b][7]=y.w;
            }
        }

        __syncthreads();
        if (c + 2 < NCHUNK)
            issue_chunk(c0g + c + 2, (c + 2) % NBUF, smem_base, mbar_base, tid);

        mbar_wait(mbar_base + buf * 8, (c / NBUF) & 1);

        if (active) {
            const ull* wt = (const ull*)(wst + buf * WBUF) + g * WTILE_ULL + j;

            ull a[4][8];
            #pragma unroll
            for (int b = 0; b < 4; b++)
                #pragma unroll
                for (int k = 0; k < 8; k++) a[b][k] = 0ULL;
            #pragma unroll
            for (int e = 0; e < 8; e++) {
                const ull* wte = wt + e * 80;
                ull ue0 = bcast2(ur[0][e]);
                ull ue1 = bcast2(ur[1][e]);
                ull ue2 = bcast2(ur[2][e]);
                ull ue3 = bcast2(ur[3][e]);
                #pragma unroll
                for (int k = 0; k < 8; k++) {
                    ull wv = wte[k * 10];
                    a[0][k] = fma2(ue0, wv, a[0][k]);
                    a[1][k] = fma2(ue1, wv, a[1][k]);
                    a[2][k] = fma2(ue2, wv, a[2][k]);
                    a[3][k] = fma2(ue3, wv, a[3][k]);
                }
            }

            float ex[4];
            #pragma unroll
            for (int b = 0; b < 4; b++) {
                const ull* vsb = (const ull*)(vsb0 + b * NJ * VROW);
                ull da = 0ULL, db = 0ULL;
                #pragma unroll
                for (int k = 0; k < 4; k++) {
                    da = fma2(a[b][k],     vsb[k],     da);
                    db = fma2(a[b][k + 4], vsb[k + 4], db);
                }
                ex[b] = __expf(sum2(add2(da, db)));
            }

            const unsigned M = 0x3FFFFFFFu;
            #pragma unroll
            for (int b = 0; b < 4; b++) {
                float s5 = ex[b] + __shfl_sync(M, ex[b], sl5);
                float as = s5 + __shfl_sync(M, s5, sl1);
                float bs = as + __shfl_sync(M, as, sl2);
                float tt = bs + __shfl_sync(M, s5, sl4);
                g_c[((size_t)(b0 + b) * NI + i) * NJ + j] = __fdividef(ex[b], tt);
            }
        }
    }
}

template <bool FIRST, bool LAST>
__global__ void reduce_kernel(float* __restrict__ out) {
    int t = blockIdx.x * blockDim.x + threadIdx.x;
    if (t >= B_ * NJ * 4) return;
    int q = t & 3;
    int j = (t >> 2) % NJ;
    int b = t / (NJ * 4);

    const float4* src = (const float4*)g_partial + ((size_t)(b * NPART) * NJ + j) * 4 + q;
    float4 acc = make_float4(0.f, 0.f, 0.f, 0.f);
    #pragma unroll
    for (int p = 0; p < NPART; p++) {
        float4 x = src[(size_t)p * NJ * 4];
        acc.x += x.x; acc.y += x.y; acc.z += x.z; acc.w += x.w;
    }

    float sq = acc.x * acc.x + acc.y * acc.y + acc.z * acc.z + acc.w * acc.w;
    sq += __shfl_xor_sync(0xFFFFFFFFu, sq, 1);
    sq += __shfl_xor_sync(0xFFFFFFFFu, sq, 2);
    float norm = sqrtf(sq);
    float factor = sq / (norm * (1.f + sq));

    float4 v = make_float4(factor * acc.x, factor * acc.y, factor * acc.z, factor * acc.w);
    if (LAST) {
        ((float4*)out)[(size_t)(b * NJ + j) * 4 + q] = v;
    } else {
        float4* vp = (float4*)g_vsum + (b * NJ + j) * 4 + q;
        if (FIRST) {
            *vp = v;
        } else {
            float4 o = *vp;
            *vp = make_float4(o.x + v.x, o.y + v.y, o.z + v.z, o.w + v.w);
        }
    }
}

extern "C" void kernel_launch(void* const* d_in, const int* in_sizes, int n_in,
                              void* d_out, int out_size) {
    const float* u = (const float*)d_in[0];
    const float* W = (const float*)d_in[1];
    float* out = (float*)d_out;

    const int smem = SMEM_WORDS * 4;
    cudaFuncSetAttribute(sweepB_kernel<true>,  cudaFuncAttributeMaxDynamicSharedMemorySize, smem);
    cudaFuncSetAttribute(sweepB_kernel<false>, cudaFuncAttributeMaxDynamicSharedMemorySize, smem);
    cudaFuncSetAttribute(sweepA_kernel,        cudaFuncAttributeMaxDynamicSharedMemorySize, smem);

    dim3 grid(ISPLITS, B_ / BTF);                            // 8 x 32
    const int rblocks = (B_ * NJ * 4 + 255) / 256;           // 80
    const int pthreads = NI * NJ * DI;
    const int pblocks = (pthreads + 255) / 256;

    prepack_kernel<<<pblocks, 256>>>(W);                      // 0
    sweepB_kernel<true><<<grid, THREADS, smem>>>(u);          // 1  (c = 0.1)
    reduce_kernel<true, false><<<rblocks, 256>>>(out);        // 2  (vsum = v1)
    sweepA_kernel<<<grid, THREADS, smem>>>(u);                // 3  (c2)
    sweepB_kernel<false><<<grid, THREADS, smem>>>(u);         // 4  (s2)
    reduce_kernel<false, false><<<rblocks, 256>>>(out);       // 5  (vsum += v2)
    sweepA_kernel<<<grid, THREADS, smem>>>(u);                // 6  (c3)
    sweepB_kernel<false><<<grid, THREADS, smem>>>(u);         // 7  (s3)
    reduce_kernel<false, true><<<rblocks, 256>>>(out);        // 8  (out = v3)
}

// round 14
// speedup vs baseline: 1.4383x; 1.4383x over previous
#include <cuda_runtime.h>
#include <cstdint>

// DigitCaps dynamic routing, fused.
// b_t[i,j] = u_hat[b,i,j,:] . Vsum_t[b,j,:], Vsum_t = sum_{tau<t} v_tau
// W prepacked [chunk][g][e][dpair][j]; ONE cp.async.bulk per chunk; 3-slot ring.
// Both sweeps: 4 batches/thread (W-LDS wavefronts per batch halved).
// non-FIRST: 1 block/SM (reg budget 255), logit + 4-shfl cyclic softmax.

#define B_      512
#define NI      1152
#define NJ      10
#define DI      8
#define DO      16

#define THREADS 256
#define BTF     16       // batches per block (both sweeps)
#define G_      6
#define ISPLITS 8
#define ICHUNK  144
#define NCHUNK  24
#define NCHUNK_TOTAL (ISPLITS * NCHUNK)
#define NPART   ISPLITS

#define WTILE_ULL  644
#define WBUF_ULL   (G_ * WTILE_ULL)
#define WBUF       (WBUF_ULL * 2)
#define NBUF    3
#define VROW    18
#define CHUNK_BYTES (WBUF * 4)
#define MBAR_OFF   (NBUF * WBUF + BTF * NJ * VROW)
#define SMEM_WORDS (MBAR_OFF + 8)

__device__ float g_wpad[(size_t)NCHUNK_TOTAL * WBUF];
__device__ float g_partial[(size_t)B_ * NPART * NJ * DO];
__device__ float g_vsum[B_ * NJ * DO];

using ull = unsigned long long;

__device__ __forceinline__ ull fma2(ull a, ull b, ull c) {
    ull d; asm("fma.rn.f32x2 %0, %1, %2, %3;" : "=l"(d) : "l"(a), "l"(b), "l"(c)); return d;
}
__device__ __forceinline__ ull add2(ull a, ull b) {
    ull d; asm("add.rn.f32x2 %0, %1, %2;" : "=l"(d) : "l"(a), "l"(b)); return d;
}
__device__ __forceinline__ ull bcast2(float x) {
    ull d; asm("mov.b64 %0, {%1, %1};" : "=l"(d) : "f"(x)); return d;
}
__device__ __forceinline__ ull pack2(float x, float y) {
    ull d; asm("mov.b64 %0, {%1, %2};" : "=l"(d) : "f"(x), "f"(y)); return d;
}
__device__ __forceinline__ float sum2(ull a) {
    float l, h; asm("mov.b64 {%0, %1}, %2;" : "=f"(l), "=f"(h) : "l"(a)); return l + h;
}
__device__ __forceinline__ void st2(float* p, ull v) { *(ull*)p = v; }

__device__ __forceinline__ void mbar_init(uint32_t addr, uint32_t count) {
    asm volatile("mbarrier.init.shared.b64 [%0], %1;" :: "r"(addr), "r"(count) : "memory");
}
__device__ __forceinline__ void mbar_wait(uint32_t addr, uint32_t parity) {
    asm volatile(
        "{\n\t.reg .pred P;\n\t"
        "WL_%=:\n\t"
        "mbarrier.try_wait.parity.acquire.cta.shared::cta.b64 P, [%0], %1, 0x989680;\n\t"
        "@P bra.uni WD_%=;\n\t"
        "bra.uni WL_%=;\n\t"
        "WD_%=:\n\t}"
        :: "r"(addr), "r"(parity) : "memory");
}

__device__ __forceinline__ void issue_chunk(int chunk, int slot,
                                            uint32_t sbase, uint32_t mbase, int tid) {
    if (tid == 0) {
        uint32_t mbar = mbase + slot * 8;
        asm volatile("mbarrier.arrive.expect_tx.shared.b64 _, [%0], %1;"
                     :: "r"(mbar), "r"((uint32_t)CHUNK_BYTES) : "memory");
        const float* src = g_wpad + (size_t)chunk * WBUF;
        uint32_t dst = sbase + (uint32_t)(slot * WBUF) * 4;
        asm volatile(
            "cp.async.bulk.shared::cluster.global.mbarrier::complete_tx::bytes "
            "[%0], [%1], %2, [%3];"
            :: "r"(dst), "l"(src), "r"((uint32_t)CHUNK_BYTES), "r"(mbar) : "memory");
    }
}

// W[i][j][e][d] -> g_wpad ull[chunk*WBUF_ULL + g*644 + e*80 + k*10 + j]
__global__ void prepack_kernel(const float* __restrict__ W) {
    int t = blockIdx.x * blockDim.x + threadIdx.x;
    if (t >= NI * NJ * DI) return;
    int e = t % DI;
    int r = t / DI;
    int j = r % NJ;
    int i = r / NJ;
    int chunk = i / G_;
    int g = i - chunk * G_;
    const float4* src = (const float4*)(W + (((size_t)(i * NJ + j)) * DI + e) * DO);
    float4 v0 = src[0], v1 = src[1], v2 = src[2], v3 = src[3];
    ull* dst = (ull*)g_wpad + (size_t)chunk * WBUF_ULL + g * WTILE_ULL + e * 80 + j;
    dst[0]  = pack2(v0.x, v0.y);
    dst[10] = pack2(v0.z, v0.w);
    dst[20] = pack2(v1.x, v1.y);
    dst[30] = pack2(v1.z, v1.w);
    dst[40] = pack2(v2.x, v2.y);
    dst[50] = pack2(v2.z, v2.w);
    dst[60] = pack2(v3.x, v3.y);
    dst[70] = pack2(v3.z, v3.w);
}

// ---------------- FIRST: uniform c=0.1, 4 batches/thread (proven 30us) ----------------
__global__ void __launch_bounds__(THREADS, 2)
sweep_first_kernel(const float* __restrict__ u) {
    extern __shared__ float smem[];
    float* wst = smem;
    float* red = smem;

    const int tid  = threadIdx.x;
    const int lane = tid & 31;
    const int warp = tid >> 5;
    const int seg  = lane / 10;
    const bool active = (seg < 3);
    const int j    = lane - seg * 10;
    const int unit = warp * 3 + (active ? seg : 0);
    const int bq   = unit & 3;
    const int g    = unit >> 2;

    const int c0g   = blockIdx.x * NCHUNK;
    const int i0    = blockIdx.x * ICHUNK;
    const int bbase = blockIdx.y * BTF;

    uint32_t smem_base = (uint32_t)__cvta_generic_to_shared(wst);
    uint32_t mbar_base = (uint32_t)__cvta_generic_to_shared(smem + MBAR_OFF);

    if (tid == 0) {
        mbar_init(mbar_base + 0, 1);
        mbar_init(mbar_base + 8, 1);
        mbar_init(mbar_base + 16, 1);
    }
    __syncthreads();

    issue_chunk(c0g, 0, smem_base, mbar_base, tid);
    issue_chunk(c0g + 1, 1, smem_base, mbar_base, tid);

    ull sacc[4][8];
    #pragma unroll
    for (int b = 0; b < 4; b++)
        #pragma unroll
        for (int k = 0; k < 8; k++) sacc[b][k] = 0ULL;

    const int b0 = bbase + bq * 4;
    const float* up = u + (size_t)b0 * NI * DI;

    for (int c = 0; c < NCHUNK; c++) {
        const int buf = c % NBUF;
        const int i = i0 + c * G_ + g;

        float ur[4][8];
        if (active) {
            #pragma unroll
            for (int b = 0; b < 4; b++) {
                const float4* s = (const float4*)(up + (size_t)b * NI * DI + (size_t)i * DI);
                float4 x = s[0], y = s[1];
                ur[b][0]=x.x; ur[b][1]=x.y; ur[b][2]=x.z; ur[b][3]=x.w;
                ur[b][4]=y.x; ur[b][5]=y.y; ur[b][6]=y.z; ur[b][7]=y.w;
            }
        }

        __syncthreads();
        if (c + 2 < NCHUNK)
            issue_chunk(c0g + c + 2, (c + 2) % NBUF, smem_base, mbar_base, tid);

        mbar_wait(mbar_base + buf * 8, (c / NBUF) & 1);

        if (active) {
            const ull* wt = (const ull*)(wst + buf * WBUF) + g * WTILE_ULL + j;
            #pragma unroll
            for (int e = 0; e < 8; e++) {
                const ull* wte = wt + e * 80;
                ull ue0 = bcast2(ur[0][e]);
                ull ue1 = bcast2(ur[1][e]);
                ull ue2 = bcast2(ur[2][e]);
                ull ue3 = bcast2(ur[3][e]);
                #pragma unroll
                for (int k = 0; k < 8; k++) {
                    ull wv = wte[k * 10];
                    sacc[0][k] = fma2(ue0, wv, sacc[0][k]);
                    sacc[1][k] = fma2(ue1, wv, sacc[1][k]);
                    sacc[2][k] = fma2(ue2, wv, sacc[2][k]);
                    sacc[3][k] = fma2(ue3, wv, sacc[3][k]);
                }
            }
        }
    }

    __syncthreads();
    if (active) {
        #pragma unroll
        for (int b = 0; b < 4; b++) {
            int r = ((bq * 4 + b) * 6 + g) * 10 + j;
            #pragma unroll
            for (int k = 0; k < 8; k++)
                st2(red + r * 16 + 2 * k, sacc[b][k]);
        }
    }
    __syncthreads();

    #pragma unroll 1
    for (int idx = tid; idx < BTF * NJ * DO; idx += THREADS) {
        int d  = idx & 15;
        int r  = idx >> 4;
        int jj = r % 10;
        int bt = r / 10;
        float s = 0.f;
        #pragma unroll
        for (int gg = 0; gg < 6; gg++)
            s += red[((bt * 6 + gg) * 10 + jj) * 16 + d];
        s *= 0.1f;
        int b = bbase + bt;
        g_partial[((size_t)(b * NPART + blockIdx.x) * NJ + jj) * DO + d] = s;
    }
}

// ---- non-FIRST: fused routing sweep, 4 batches/thread, 1 block/SM ----
__global__ void __launch_bounds__(THREADS, 1)
sweep_kernel(const float* __restrict__ u) {
    extern __shared__ float smem[];
    float* wst = smem;
    float* vsm = smem + NBUF * WBUF;
    float* red = smem;

    const int tid  = threadIdx.x;
    const int lane = tid & 31;
    const int warp = tid >> 5;
    const int seg  = lane / 10;
    const bool active = (seg < 3);
    const int j    = lane - seg * 10;
    const int unit = warp * 3 + (active ? seg : 0);
    const int bq   = unit & 3;
    const int g    = unit >> 2;

    const int base = seg * 10;
    const int sl5 = base + (j >= 5 ? j - 5 : j + 5);
    const int sl1 = base + (j >= 9 ? j - 9 : j + 1);
    const int sl2 = base + (j >= 8 ? j - 8 : j + 2);
    const int sl4 = base + (j >= 6 ? j - 6 : j + 4);

    const int c0g   = blockIdx.x * NCHUNK;
    const int i0    = blockIdx.x * ICHUNK;
    const int bbase = blockIdx.y * BTF;

    uint32_t smem_base = (uint32_t)__cvta_generic_to_shared(wst);
    uint32_t mbar_base = (uint32_t)__cvta_generic_to_shared(smem + MBAR_OFF);

    if (tid == 0) {
        mbar_init(mbar_base + 0, 1);
        mbar_init(mbar_base + 8, 1);
        mbar_init(mbar_base + 16, 1);
    }
    for (int idx = tid; idx < BTF * NJ * DO; idx += THREADS) {
        vsm[(idx >> 4) * VROW + (idx & 15)] = g_vsum[bbase * NJ * DO + idx];
    }
    __syncthreads();

    issue_chunk(c0g, 0, smem_base, mbar_base, tid);
    issue_chunk(c0g + 1, 1, smem_base, mbar_base, tid);

    ull sacc[4][8];
    #pragma unroll
    for (int b = 0; b < 4; b++)
        #pragma unroll
        for (int k = 0; k < 8; k++) sacc[b][k] = 0ULL;

    const int b0 = bbase + bq * 4;
    const float* up = u + (size_t)b0 * NI * DI;
    const float* vsb0 = vsm + ((bq * 4) * NJ + j) * VROW;

    for (int c = 0; c < NCHUNK; c++) {
        const int buf = c % NBUF;
        const int i = i0 + c * G_ + g;

        float ur[4][8];
        if (active) {
            #pragma unroll
            for (int b = 0; b < 4; b++) {
                const float4* s = (const float4*)(up + (size_t)b * NI * DI + (size_t)i * DI);
                float4 x = s[0], y = s[1];
                ur[b][0]=x.x; ur[b][1]=x.y; ur[b][2]=x.z; ur[b][3]=x.w;
                ur[b][4]=y.x; ur[b][5]=y.y; ur[b][6]=y.z; ur[b][7]=y.w;
            }
        }

        __syncthreads();
        if (c + 2 < NCHUNK)
            issue_chunk(c0g + c + 2, (c + 2) % NBUF, smem_base, mbar_base, tid);

        mbar_wait(mbar_base + buf * 8, (c / NBUF) & 1);

        if (active) {
            const ull* wt = (const ull*)(wst + buf * WBUF) + g * WTILE_ULL + j;

            ull a[4][8];
            #pragma unroll
            for (int b = 0; b < 4; b++)
                #pragma unroll
                for (int k = 0; k < 8; k++) a[b][k] = 0ULL;
            #pragma unroll
            for (int e = 0; e < 8; e++) {
                const ull* wte = wt + e * 80;
                ull ue0 = bcast2(ur[0][e]);
                ull ue1 = bcast2(ur[1][e]);
                ull ue2 = bcast2(ur[2][e]);
                ull ue3 = bcast2(ur[3][e]);
                #pragma unroll
                for (int k = 0; k < 8; k++) {
                    ull wv = wte[k * 10];
                    a[0][k] = fma2(ue0, wv, a[0][k]);
                    a[1][k] = fma2(ue1, wv, a[1][k]);
                    a[2][k] = fma2(ue2, wv, a[2][k]);
                    a[3][k] = fma2(ue3, wv, a[3][k]);
                }
            }

            // logits, two chains per batch
            float ex[4];
            #pragma unroll
            for (int b = 0; b < 4; b++) {
                const ull* vsb = (const ull*)(vsb0 + b * NJ * VROW);
                ull da = 0ULL, db = 0ULL;
                #pragma unroll
                for (int k = 0; k < 4; k++) {
                    da = fma2(a[b][k],     vsb[k],     da);
                    db = fma2(a[b][k + 4], vsb[k + 4], db);
                }
                ex[b] = __expf(sum2(add2(da, db)));
            }

            // 10-lane cyclic softmax sums, 4 batches interleaved
            const unsigned M = 0x3FFFFFFFu;
            float s5[4], as[4], bs[4], tt[4];
            #pragma unroll
            for (int b = 0; b < 4; b++) s5[b] = ex[b] + __shfl_sync(M, ex[b], sl5);
            #pragma unroll
            for (int b = 0; b < 4; b++) as[b] = s5[b] + __shfl_sync(M, s5[b], sl1);
            #pragma unroll
            for (int b = 0; b < 4; b++) bs[b] = as[b] + __shfl_sync(M, as[b], sl2);
            #pragma unroll
            for (int b = 0; b < 4; b++) tt[b] = bs[b] + __shfl_sync(M, s5[b], sl4);

            #pragma unroll
            for (int b = 0; b < 4; b++) {
                ull cb = bcast2(__fdividef(ex[b], tt[b]));
                #pragma unroll
                for (int k = 0; k < 8; k++)
                    sacc[b][k] = fma2(cb, a[b][k], sacc[b][k]);
            }
        }
    }

    // ---- in-block reduction over g ----
    __syncthreads();
    if (active) {
        #pragma unroll
        for (int b = 0; b < 4; b++) {
            int r = ((bq * 4 + b) * 6 + g) * 10 + j;
            #pragma unroll
            for (int k = 0; k < 8; k++)
                st2(red + r * 16 + 2 * k, sacc[b][k]);
        }
    }
    __syncthreads();

    #pragma unroll 1
    for (int idx = tid; idx < BTF * NJ * DO; idx += THREADS) {
        int d  = idx & 15;
        int r  = idx >> 4;
        int jj = r % 10;
        int bt = r / 10;
        float s = 0.f;
        #pragma unroll
        for (int gg = 0; gg < 6; gg++)
            s += red[((bt * 6 + gg) * 10 + jj) * 16 + d];
        int b = bbase + bt;
        g_partial[((size_t)(b * NPART + blockIdx.x) * NJ + jj) * DO + d] = s;
    }
}

template <bool FIRST, bool LAST>
__global__ void reduce_kernel(float* __restrict__ out) {
    int t = blockIdx.x * blockDim.x + threadIdx.x;
    if (t >= B_ * NJ * 4) return;
    int q = t & 3;
    int j = (t >> 2) % NJ;
    int b = t / (NJ * 4);

    const float4* src = (const float4*)g_partial + ((size_t)(b * NPART) * NJ + j) * 4 + q;
    float4 acc = make_float4(0.f, 0.f, 0.f, 0.f);
    #pragma unroll
    for (int p = 0; p < NPART; p++) {
        float4 x = src[(size_t)p * NJ * 4];
        acc.x += x.x; acc.y += x.y; acc.z += x.z; acc.w += x.w;
    }

    float sq = acc.x * acc.x + acc.y * acc.y + acc.z * acc.z + acc.w * acc.w;
    sq += __shfl_xor_sync(0xFFFFFFFFu, sq, 1);
    sq += __shfl_xor_sync(0xFFFFFFFFu, sq, 2);
    float norm = sqrtf(sq);
    float factor = sq / (norm * (1.f + sq));

    float4 v = make_float4(factor * acc.x, factor * acc.y, factor * acc.z, factor * acc.w);
    if (LAST) {
        ((float4*)out)[(size_t)(b * NJ + j) * 4 + q] = v;
    } else {
        float4* vp = (float4*)g_vsum + (b * NJ + j) * 4 + q;
        if (FIRST) {
            *vp = v;
        } else {
            float4 o = *vp;
            *vp = make_float4(o.x + v.x, o.y + v.y, o.z + v.z, o.w + v.w);
        }
    }
}

extern "C" void kernel_launch(void* const* d_in, const int* in_sizes, int n_in,
                              void* d_out, int out_size) {
    const float* u = (const float*)d_in[0];
    const float* W = (const float*)d_in[1];
    float* out = (float*)d_out;

    const int smem = SMEM_WORDS * 4;
    cudaFuncSetAttribute(sweep_first_kernel, cudaFuncAttributeMaxDynamicSharedMemorySize, smem);
    cudaFuncSetAttribute(sweep_kernel,       cudaFuncAttributeMaxDynamicSharedMemorySize, smem);

    dim3 grid(ISPLITS, B_ / BTF);                            // 8 x 32 = 256 blocks
    const int rblocks = (B_ * NJ * 4 + 255) / 256;           // 80
    const int pthreads = NI * NJ * DI;
    const int pblocks = (pthreads + 255) / 256;

    prepack_kernel<<<pblocks, 256>>>(W);                      // 0
    sweep_first_kernel<<<grid, THREADS, smem>>>(u);           // 1
    reduce_kernel<true, false><<<rblocks, 256>>>(out);        // 2
    sweep_kernel<<<grid, THREADS, smem>>>(u);                 // 3
    reduce_kernel<false, false><<<rblocks, 256>>>(out);       // 4
    sweep_kernel<<<grid, THREADS, smem>>>(u);                 // 5  <- ncu -s 5
    reduce_kernel<false, true><<<rblocks, 256>>>(out);        // 6
}

// round 15
// speedup vs baseline: 1.5704x; 1.0918x over previous
#include <cuda_runtime.h>
#include <cstdint>

// DigitCaps dynamic routing, fused.
// b_t[i,j] = u_hat[b,i,j,:] . Vsum_t[b,j,:], Vsum_t = sum_{tau<t} v_tau
// W prepacked [chunk6][g][e][dpair][j]; cp.async.bulk staging, 3-slot ring.
// FIRST: G=6 chunks, 2 blocks/SM, 4 batches/thread (proven 30us).
// non-FIRST: G=12 chunks (two i's per barrier), 1 block/SM, 4 batches/thread.

#define B_      512
#define NI      1152
#define NJ      10
#define DI      8
#define DO      16

#define THREADS 256
#define BTF     16       // batches per block (both sweeps)
#define G_      6
#define ISPLITS 8
#define ICHUNK  144
#define NCHUNK  24                 // G=6 chunks per i-split
#define NCHUNK2 12                 // G=12 chunks per i-split (non-FIRST)
#define NCHUNK_TOTAL (ISPLITS * NCHUNK)
#define NPART   ISPLITS

#define WTILE_ULL  644
#define WBUF_ULL   (G_ * WTILE_ULL)       // 3864 ull per 6-i tile
#define WBUF       (WBUF_ULL * 2)         // 7728 words per 6-i tile
#define NBUF    3
#define VROW    18
#define CHUNK_BYTES  (WBUF * 4)           // 30912  (G=6)
#define CHUNK2_BYTES (2 * WBUF * 4)       // 61824  (G=12)

#define MBAR_OFF_F  (NBUF * WBUF + BTF * NJ * VROW)          // FIRST layout
#define SMEM_F      ((MBAR_OFF_F + 8) * 4)                   // 104288 B
#define MBAR_OFF_S  (NBUF * 2 * WBUF + BTF * NJ * VROW)      // non-FIRST layout
#define SMEM_S      ((MBAR_OFF_S + 8) * 4)                   // 197024 B

__device__ float g_wpad[(size_t)NCHUNK_TOTAL * WBUF];
__device__ float g_partial[(size_t)B_ * NPART * NJ * DO];
__device__ float g_vsum[B_ * NJ * DO];

using ull = unsigned long long;

__device__ __forceinline__ ull fma2(ull a, ull b, ull c) {
    ull d; asm("fma.rn.f32x2 %0, %1, %2, %3;" : "=l"(d) : "l"(a), "l"(b), "l"(c)); return d;
}
__device__ __forceinline__ ull add2(ull a, ull b) {
    ull d; asm("add.rn.f32x2 %0, %1, %2;" : "=l"(d) : "l"(a), "l"(b)); return d;
}
__device__ __forceinline__ ull bcast2(float x) {
    ull d; asm("mov.b64 %0, {%1, %1};" : "=l"(d) : "f"(x)); return d;
}
__device__ __forceinline__ ull pack2(float x, float y) {
    ull d; asm("mov.b64 %0, {%1, %2};" : "=l"(d) : "f"(x), "f"(y)); return d;
}
__device__ __forceinline__ float sum2(ull a) {
    float l, h; asm("mov.b64 {%0, %1}, %2;" : "=f"(l), "=f"(h) : "l"(a)); return l + h;
}
__device__ __forceinline__ void st2(float* p, ull v) { *(ull*)p = v; }

__device__ __forceinline__ void mbar_init(uint32_t addr, uint32_t count) {
    asm volatile("mbarrier.init.shared.b64 [%0], %1;" :: "r"(addr), "r"(count) : "memory");
}
__device__ __forceinline__ void mbar_wait(uint32_t addr, uint32_t parity) {
    asm volatile(
        "{\n\t.reg .pred P;\n\t"
        "WL_%=:\n\t"
        "mbarrier.try_wait.parity.acquire.cta.shared::cta.b64 P, [%0], %1, 0x989680;\n\t"
        "@P bra.uni WD_%=;\n\t"
        "bra.uni WL_%=;\n\t"
        "WD_%=:\n\t}"
        :: "r"(addr), "r"(parity) : "memory");
}

__device__ __forceinline__ void issue_bulk(const float* src, uint32_t dst,
                                           uint32_t bytes, uint32_t mbar) {
    asm volatile("mbarrier.arrive.expect_tx.shared.b64 _, [%0], %1;"
                 :: "r"(mbar), "r"(bytes) : "memory");
    asm volatile(
        "cp.async.bulk.shared::cluster.global.mbarrier::complete_tx::bytes "
        "[%0], [%1], %2, [%3];"
        :: "r"(dst), "l"(src), "r"(bytes), "r"(mbar) : "memory");
}

// W[i][j][e][d] -> g_wpad ull[chunk*WBUF_ULL + g*644 + e*80 + k*10 + j]
__global__ void prepack_kernel(const float* __restrict__ W) {
    int t = blockIdx.x * blockDim.x + threadIdx.x;
    if (t >= NI * NJ * DI) return;
    int e = t % DI;
    int r = t / DI;
    int j = r % NJ;
    int i = r / NJ;
    int chunk = i / G_;
    int g = i - chunk * G_;
    const float4* src = (const float4*)(W + (((size_t)(i * NJ + j)) * DI + e) * DO);
    float4 v0 = src[0], v1 = src[1], v2 = src[2], v3 = src[3];
    ull* dst = (ull*)g_wpad + (size_t)chunk * WBUF_ULL + g * WTILE_ULL + e * 80 + j;
    dst[0]  = pack2(v0.x, v0.y);
    dst[10] = pack2(v0.z, v0.w);
    dst[20] = pack2(v1.x, v1.y);
    dst[30] = pack2(v1.z, v1.w);
    dst[40] = pack2(v2.x, v2.y);
    dst[50] = pack2(v2.z, v2.w);
    dst[60] = pack2(v3.x, v3.y);
    dst[70] = pack2(v3.z, v3.w);
}

// ---------------- FIRST: uniform c=0.1, 4 batches/thread, G=6 ----------------
__global__ void __launch_bounds__(THREADS, 2)
sweep_first_kernel(const float* __restrict__ u) {
    extern __shared__ float smem[];
    float* wst = smem;
    float* red = smem;

    const int tid  = threadIdx.x;
    const int lane = tid & 31;
    const int warp = tid >> 5;
    const int seg  = lane / 10;
    const bool active = (seg < 3);
    const int j    = lane - seg * 10;
    const int unit = warp * 3 + (active ? seg : 0);
    const int bq   = unit & 3;
    const int g    = unit >> 2;

    const int c0g   = blockIdx.x * NCHUNK;
    const int i0    = blockIdx.x * ICHUNK;
    const int bbase = blockIdx.y * BTF;

    uint32_t smem_base = (uint32_t)__cvta_generic_to_shared(wst);
    uint32_t mbar_base = (uint32_t)__cvta_generic_to_shared(smem + MBAR_OFF_F);

    if (tid == 0) {
        mbar_init(mbar_base + 0, 1);
        mbar_init(mbar_base + 8, 1);
        mbar_init(mbar_base + 16, 1);
    }
    __syncthreads();

    if (tid == 0) {
        issue_bulk(g_wpad + (size_t)c0g * WBUF, smem_base, CHUNK_BYTES, mbar_base);
        issue_bulk(g_wpad + (size_t)(c0g + 1) * WBUF, smem_base + WBUF * 4,
                   CHUNK_BYTES, mbar_base + 8);
    }

    ull sacc[4][8];
    #pragma unroll
    for (int b = 0; b < 4; b++)
        #pragma unroll
        for (int k = 0; k < 8; k++) sacc[b][k] = 0ULL;

    const int b0 = bbase + bq * 4;
    const float* up = u + (size_t)b0 * NI * DI;

    for (int c = 0; c < NCHUNK; c++) {
        const int buf = c % NBUF;
        const int i = i0 + c * G_ + g;

        float ur[4][8];
        if (active) {
            #pragma unroll
            for (int b = 0; b < 4; b++) {
                const float4* s = (const float4*)(up + (size_t)b * NI * DI + (size_t)i * DI);
                float4 x = s[0], y = s[1];
                ur[b][0]=x.x; ur[b][1]=x.y; ur[b][2]=x.z; ur[b][3]=x.w;
                ur[b][4]=y.x; ur[b][5]=y.y; ur[b][6]=y.z; ur[b][7]=y.w;
            }
        }

        __syncthreads();
        if (tid == 0 && c + 2 < NCHUNK)
            issue_bulk(g_wpad + (size_t)(c0g + c + 2) * WBUF,
                       smem_base + (uint32_t)(((c + 2) % NBUF) * WBUF) * 4,
                       CHUNK_BYTES, mbar_base + ((c + 2) % NBUF) * 8);

        mbar_wait(mbar_base + buf * 8, (c / NBUF) & 1);

        if (active) {
            const ull* wt = (const ull*)(wst + buf * WBUF) + g * WTILE_ULL + j;
            #pragma unroll
            for (int e = 0; e < 8; e++) {
                const ull* wte = wt + e * 80;
                ull ue0 = bcast2(ur[0][e]);
                ull ue1 = bcast2(ur[1][e]);
                ull ue2 = bcast2(ur[2][e]);
                ull ue3 = bcast2(ur[3][e]);
                #pragma unroll
                for (int k = 0; k < 8; k++) {
                    ull wv = wte[k * 10];
                    sacc[0][k] = fma2(ue0, wv, sacc[0][k]);
                    sacc[1][k] = fma2(ue1, wv, sacc[1][k]);
                    sacc[2][k] = fma2(ue2, wv, sacc[2][k]);
                    sacc[3][k] = fma2(ue3, wv, sacc[3][k]);
                }
            }
        }
    }

    __syncthreads();
    if (active) {
        #pragma unroll
        for (int b = 0; b < 4; b++) {
            int r = ((bq * 4 + b) * 6 + g) * 10 + j;
            #pragma unroll
            for (int k = 0; k < 8; k++)
                st2(red + r * 16 + 2 * k, sacc[b][k]);
        }
    }
    __syncthreads();

    #pragma unroll 1
    for (int idx = tid; idx < BTF * NJ * DO; idx += THREADS) {
        int d  = idx & 15;
        int r  = idx >> 4;
        int jj = r % 10;
        int bt = r / 10;
        float s = 0.f;
        #pragma unroll
        for (int gg = 0; gg < 6; gg++)
            s += red[((bt * 6 + gg) * 10 + jj) * 16 + d];
        s *= 0.1f;
        int b = bbase + bt;
        g_partial[((size_t)(b * NPART + blockIdx.x) * NJ + jj) * DO + d] = s;
    }
}

// shared routing body: one i's worth of a-loop + logit + softmax + sacc update
__device__ __forceinline__ void route_i(
    const ull* __restrict__ wt, const float ur[4][8],
    const float* __restrict__ vsb0, ull sacc[4][8],
    int sl5, int sl1, int sl2, int sl4)
{
    ull a[4][8];
    #pragma unroll
    for (int b = 0; b < 4; b++)
        #pragma unroll
        for (int k = 0; k < 8; k++) a[b][k] = 0ULL;
    #pragma unroll
    for (int e = 0; e < 8; e++) {
        const ull* wte = wt + e * 80;
        ull ue0 = bcast2(ur[0][e]);
        ull ue1 = bcast2(ur[1][e]);
        ull ue2 = bcast2(ur[2][e]);
        ull ue3 = bcast2(ur[3][e]);
        #pragma unroll
        for (int k = 0; k < 8; k++) {
            ull wv = wte[k * 10];
            a[0][k] = fma2(ue0, wv, a[0][k]);
            a[1][k] = fma2(ue1, wv, a[1][k]);
            a[2][k] = fma2(ue2, wv, a[2][k]);
            a[3][k] = fma2(ue3, wv, a[3][k]);
        }
    }

    float ex[4];
    #pragma unroll
    for (int b = 0; b < 4; b++) {
        const ull* vsb = (const ull*)(vsb0 + b * NJ * VROW);
        ull da = 0ULL, db = 0ULL;
        #pragma unroll
        for (int k = 0; k < 4; k++) {
            da = fma2(a[b][k],     vsb[k],     da);
            db = fma2(a[b][k + 4], vsb[k + 4], db);
        }
        ex[b] = __expf(sum2(add2(da, db)));
    }

    const unsigned M = 0x3FFFFFFFu;
    float s5[4], as[4], bs[4], tt[4];
    #pragma unroll
    for (int b = 0; b < 4; b++) s5[b] = ex[b] + __shfl_sync(M, ex[b], sl5);
    #pragma unroll
    for (int b = 0; b < 4; b++) as[b] = s5[b] + __shfl_sync(M, s5[b], sl1);
    #pragma unroll
    for (int b = 0; b < 4; b++) bs[b] = as[b] + __shfl_sync(M, as[b], sl2);
    #pragma unroll
    for (int b = 0; b < 4; b++) tt[b] = bs[b] + __shfl_sync(M, s5[b], sl4);

    #pragma unroll
    for (int b = 0; b < 4; b++) {
        ull cb = bcast2(__fdividef(ex[b], tt[b]));
        #pragma unroll
        for (int k = 0; k < 8; k++)
            sacc[b][k] = fma2(cb, a[b][k], sacc[b][k]);
    }
}

// ---- non-FIRST: fused routing sweep, 4 batches/thread, G=12 (2 i's per wait) ----
__global__ void __launch_bounds__(THREADS, 1)
sweep_kernel(const float* __restrict__ u) {
    extern __shared__ float smem[];
    float* wst = smem;
    float* vsm = smem + NBUF * 2 * WBUF;
    float* red = smem;

    const int tid  = threadIdx.x;
    const int lane = tid & 31;
    const int warp = tid >> 5;
    const int seg  = lane / 10;
    const bool active = (seg < 3);
    const int j    = lane - seg * 10;
    const int unit = warp * 3 + (active ? seg : 0);
    const int bq   = unit & 3;
    const int g    = unit >> 2;

    const int base = seg * 10;
    const int sl5 = base + (j >= 5 ? j - 5 : j + 5);
    const int sl1 = base + (j >= 9 ? j - 9 : j + 1);
    const int sl2 = base + (j >= 8 ? j - 8 : j + 2);
    const int sl4 = base + (j >= 6 ? j - 6 : j + 4);

    const int c0g2  = blockIdx.x * NCHUNK2;   // 12-i chunk index base
    const int i0    = blockIdx.x * ICHUNK;
    const int bbase = blockIdx.y * BTF;

    uint32_t smem_base = (uint32_t)__cvta_generic_to_shared(wst);
    uint32_t mbar_base = (uint32_t)__cvta_generic_to_shared(smem + MBAR_OFF_S);

    if (tid == 0) {
        mbar_init(mbar_base + 0, 1);
        mbar_init(mbar_base + 8, 1);
        mbar_init(mbar_base + 16, 1);
    }
    for (int idx = tid; idx < BTF * NJ * DO; idx += THREADS) {
        vsm[(idx >> 4) * VROW + (idx & 15)] = g_vsum[bbase * NJ * DO + idx];
    }
    __syncthreads();

    if (tid == 0) {
        issue_bulk(g_wpad + (size_t)c0g2 * 2 * WBUF, smem_base, CHUNK2_BYTES, mbar_base);
        issue_bulk(g_wpad + (size_t)(c0g2 + 1) * 2 * WBUF, smem_base + 2 * WBUF * 4,
                   CHUNK2_BYTES, mbar_base + 8);
    }

    ull sacc[4][8];
    #pragma unroll
    for (int b = 0; b < 4; b++)
        #pragma unroll
        for (int k = 0; k < 8; k++) sacc[b][k] = 0ULL;

    const int b0 = bbase + bq * 4;
    const float* up = u + (size_t)b0 * NI * DI;
    const float* vsb0 = vsm + ((bq * 4) * NJ + j) * VROW;

    for (int c = 0; c < NCHUNK2; c++) {
        const int buf = c % NBUF;
        const int ia = i0 + c * 12 + g;       // first half i
        const int ib = ia + 6;                // second half i

        float ur[4][8];
        if (active) {
            #pragma unroll
            for (int b = 0; b < 4; b++) {
                const float4* s = (const float4*)(up + (size_t)b * NI * DI + (size_t)ia * DI);
                float4 x = s[0], y = s[1];
                ur[b][0]=x.x; ur[b][1]=x.y; ur[b][2]=x.z; ur[b][3]=x.w;
                ur[b][4]=y.x; ur[b][5]=y.y; ur[b][6]=y.z; ur[b][7]=y.w;
            }
        }

        __syncthreads();   // all warps done with chunk c-1 -> its slot reusable
        if (tid == 0 && c + 2 < NCHUNK2)
            issue_bulk(g_wpad + (size_t)(c0g2 + c + 2) * 2 * WBUF,
                       smem_base + (uint32_t)(((c + 2) % NBUF) * 2 * WBUF) * 4,
                       CHUNK2_BYTES, mbar_base + ((c + 2) % NBUF) * 8);

        mbar_wait(mbar_base + buf * 8, (c / NBUF) & 1);

        if (active) {
            const ull* slot = (const ull*)(wst + buf * 2 * WBUF);
            // half A
            route_i(slot + g * WTILE_ULL + j, ur, vsb0, sacc, sl5, sl1, sl2, sl4);
            // load half-B u, then process
            #pragma unroll
            for (int b = 0; b < 4; b++) {
                const float4* s = (const float4*)(up + (size_t)b * NI * DI + (size_t)ib * DI);
                float4 x = s[0], y = s[1];
                ur[b][0]=x.x; ur[b][1]=x.y; ur[b][2]=x.z; ur[b][3]=x.w;
                ur[b][4]=y.x; ur[b][5]=y.y; ur[b][6]=y.z; ur[b][7]=y.w;
            }
            route_i(slot + WBUF_ULL + g * WTILE_ULL + j, ur, vsb0, sacc, sl5, sl1, sl2, sl4);
        }
    }

    // ---- in-block reduction over g ----
    __syncthreads();
    if (active) {
        #pragma unroll
        for (int b = 0; b < 4; b++) {
            int r = ((bq * 4 + b) * 6 + g) * 10 + j;
            #pragma unroll
            for (int k = 0; k < 8; k++)
                st2(red + r * 16 + 2 * k, sacc[b][k]);
        }
    }
    __syncthreads();

    #pragma unroll 1
    for (int idx = tid; idx < BTF * NJ * DO; idx += THREADS) {
        int d  = idx & 15;
        int r  = idx >> 4;
        int jj = r % 10;
        int bt = r / 10;
        float s = 0.f;
        #pragma unroll
        for (int gg = 0; gg < 6; gg++)
            s += red[((bt * 6 + gg) * 10 + jj) * 16 + d];
        int b = bbase + bt;
        g_partial[((size_t)(b * NPART + blockIdx.x) * NJ + jj) * DO + d] = s;
    }
}

template <bool FIRST, bool LAST>
__global__ void reduce_kernel(float* __restrict__ out) {
    int t = blockIdx.x * blockDim.x + threadIdx.x;
    if (t >= B_ * NJ * 4) return;
    int q = t & 3;
    int j = (t >> 2) % NJ;
    int b = t / (NJ * 4);

    const float4* src = (const float4*)g_partial + ((size_t)(b * NPART) * NJ + j) * 4 + q;
    float4 acc = make_float4(0.f, 0.f, 0.f, 0.f);
    #pragma unroll
    for (int p = 0; p < NPART; p++) {
        float4 x = src[(size_t)p * NJ * 4];
        acc.x += x.x; acc.y += x.y; acc.z += x.z; acc.w += x.w;
    }

    float sq = acc.x * acc.x + acc.y * acc.y + acc.z * acc.z + acc.w * acc.w;
    sq += __shfl_xor_sync(0xFFFFFFFFu, sq, 1);
    sq += __shfl_xor_sync(0xFFFFFFFFu, sq, 2);
    float norm = sqrtf(sq);
    float factor = sq / (norm * (1.f + sq));

    float4 v = make_float4(factor * acc.x, factor * acc.y, factor * acc.z, factor * acc.w);
    if (LAST) {
        ((float4*)out)[(size_t)(b * NJ + j) * 4 + q] = v;
    } else {
        float4* vp = (float4*)g_vsum + (b * NJ + j) * 4 + q;
        if (FIRST) {
            *vp = v;
        } else {
            float4 o = *vp;
            *vp = make_float4(o.x + v.x, o.y + v.y, o.z + v.z, o.w + v.w);
        }
    }
}

extern "C" void kernel_launch(void* const* d_in, const int* in_sizes, int n_in,
                              void* d_out, int out_size) {
    const float* u = (const float*)d_in[0];
    const float* W = (const float*)d_in[1];
    float* out = (float*)d_out;

    cudaFuncSetAttribute(sweep_first_kernel, cudaFuncAttributeMaxDynamicSharedMemorySize, SMEM_F);
    cudaFuncSetAttribute(sweep_kernel,       cudaFuncAttributeMaxDynamicSharedMemorySize, SMEM_S);

    dim3 grid(ISPLITS, B_ / BTF);                            // 8 x 32 = 256 blocks
    const int rblocks = (B_ * NJ * 4 + 255) / 256;           // 80
    const int pthreads = NI * NJ * DI;
    const int pblocks = (pthreads + 255) / 256;

    prepack_kernel<<<pblocks, 256>>>(W);                      // 0
    sweep_first_kernel<<<grid, THREADS, SMEM_F>>>(u);         // 1
    reduce_kernel<true, false><<<rblocks, 256>>>(out);        // 2
    sweep_kernel<<<grid, THREADS, SMEM_S>>>(u);               // 3
    reduce_kernel<false, false><<<rblocks, 256>>>(out);       // 4
    sweep_kernel<<<grid, THREADS, SMEM_S>>>(u);               // 5  <- ncu -s 5
    reduce_kernel<false, true><<<rblocks, 256>>>(out);        // 6
}